// round 11
// baseline (speedup 1.0000x reference)
#include <cuda_runtime.h>

// Problem constants (fixed shapes from reference):
//   x : (2, 128, 96, 96) f32, w{q,k,v} : (4, 32, 32) f32
//   K = 5 window, reflect pad 2, G = 4 groups of 32 channels.
#define BB   2
#define GG   4
#define CIN  32
#define CON  32
#define HHN  96
#define WWN  96
#define HWSZ (HHN * WWN)
#define CTOT 128

// Scratch for the three 1x1-conv outputs (q, k, v), each (B, 128, 96, 96).
__device__ __align__(256) float g_q[BB * CTOT * HWSZ];
__device__ __align__(256) float g_k[BB * CTOT * HWSZ];
__device__ __align__(256) float g_v[BB * CTOT * HWSZ];

// -----------------------------------------------------------------------------
// Kernel A: grouped 1x1 convs (q, k, v) fused — one CTA per (b, g, h) row.
// Byte-identical compute to the measured-best variant; only change is a bg
// offset so the grid can be launched in 4 chunks for cross-kernel overlap.
// Ledger: f32x2 mainloop, smem-bounce epilogue, small-tile/high-occupancy
// variants ALL regressed this kernel. Do not touch the inner loop.
// -----------------------------------------------------------------------------
__global__ __launch_bounds__(256, 2) void qkv_kernel(
    const float* __restrict__ x,
    const float* __restrict__ wq,
    const float* __restrict__ wk,
    const float* __restrict__ wv,
    int bgoff)
{
    __shared__ float xs[CIN * WWN];            // 12 KB
    __shared__ float wqs[CON * 33];            // padded stride 33
    __shared__ float wks[CON * 33];
    __shared__ float wvs[CON * 33];

    const int h   = blockIdx.x;
    const int bg  = blockIdx.y + bgoff;        // b*G + g
    const int g   = bg & (GG - 1);
    const int tid = threadIdx.x;

    // Stage x row: x[bg*32 + i][h][w]
    const float* xbase = x + (size_t)bg * CIN * HWSZ + (size_t)h * WWN;
    #pragma unroll
    for (int idx = tid; idx < CIN * (WWN / 4); idx += 256) {
        int i  = idx / (WWN / 4);
        int w4 = idx - i * (WWN / 4);
        reinterpret_cast<float4*>(xs)[i * (WWN / 4) + w4] =
            reinterpret_cast<const float4*>(xbase + (size_t)i * HWSZ)[w4];
    }
    // Stage weights of this group
    const float* wqg = wq + (size_t)g * CON * CIN;
    const float* wkg = wk + (size_t)g * CON * CIN;
    const float* wvg = wv + (size_t)g * CON * CIN;
    #pragma unroll
    for (int idx = tid; idx < CON * CIN; idx += 256) {
        int o = idx >> 5;
        int i = idx & 31;
        wqs[o * 33 + i] = wqg[idx];
        wks[o * 33 + i] = wkg[idx];
        wvs[o * 33 + i] = wvg[idx];
    }
    __syncthreads();

    const int o    = tid >> 3;            // 0..31 output channel
    const int wseg = (tid & 7) * 12;      // 12 consecutive w positions

    float aq[12], ak[12], av[12];
    #pragma unroll
    for (int u = 0; u < 12; u++) { aq[u] = 0.f; ak[u] = 0.f; av[u] = 0.f; }

    #pragma unroll 8
    for (int i = 0; i < CIN; i++) {
        const float wqv = wqs[o * 33 + i];
        const float wkv = wks[o * 33 + i];
        const float wvv = wvs[o * 33 + i];
        const float4* xv = reinterpret_cast<const float4*>(&xs[i * WWN + wseg]);
        float4 x0 = xv[0], x1 = xv[1], x2 = xv[2];
        float xr[12] = { x0.x, x0.y, x0.z, x0.w,
                         x1.x, x1.y, x1.z, x1.w,
                         x2.x, x2.y, x2.z, x2.w };
        #pragma unroll
        for (int u = 0; u < 12; u++) {
            aq[u] = fmaf(xr[u], wqv, aq[u]);
            ak[u] = fmaf(xr[u], wkv, ak[u]);
            av[u] = fmaf(xr[u], wvv, av[u]);
        }
    }

    const size_t obase = (size_t)(bg * CON + o) * HWSZ + (size_t)h * WWN + wseg;
    float4* qo = reinterpret_cast<float4*>(&g_q[obase]);
    float4* ko = reinterpret_cast<float4*>(&g_k[obase]);
    float4* vo = reinterpret_cast<float4*>(&g_v[obase]);
    #pragma unroll
    for (int u = 0; u < 3; u++) {
        qo[u] = make_float4(aq[4*u], aq[4*u+1], aq[4*u+2], aq[4*u+3]);
        ko[u] = make_float4(ak[4*u], ak[4*u+1], ak[4*u+2], ak[4*u+3]);
        vo[u] = make_float4(av[4*u], av[4*u+1], av[4*u+2], av[4*u+3]);
    }
}

// -----------------------------------------------------------------------------
// Kernel B: per-channel 5x5 windowed softmax with reflect indexing.
// Byte-identical compute to the measured-best variant (LDS.128 halo, stride
// 44, 256 threads, 4 outputs/thread); only change is a channel offset so the
// grid can be launched in 4 chunks for cross-kernel overlap.
// -----------------------------------------------------------------------------
__device__ __forceinline__ int refl(int i, int n) {
    return i < 0 ? -i : (i >= n ? 2 * n - 2 - i : i);
}

__device__ __forceinline__ float ex2(float x) {
    float y;
    asm("ex2.approx.ftz.f32 %0, %1;" : "=f"(y) : "f"(x));
    return y;
}

#define HALO 36
#define HSTR 44

__global__ __launch_bounds__(256) void attn_kernel(float* __restrict__ out,
                                                   int choff)
{
    __shared__ __align__(16) float ks[HALO * HSTR];   // 6.3 KB
    __shared__ __align__(16) float vs[HALO * HSTR];

    const int ch  = blockIdx.z + choff;       // 0..255 = b*128 + channel
    const int h0  = blockIdx.y * 32;
    const int w0  = blockIdx.x * 32;
    const int tid = threadIdx.x;
    const int tx  = tid & 7;                  // 8 threads across w (4 outputs each)
    const int ty  = tid >> 3;                 // 32 rows

    const size_t cbase = (size_t)ch * HWSZ;

    // Stage k/v halos (36x36 window, reflect at global borders).
    #pragma unroll
    for (int idx = tid; idx < HALO * HALO; idx += 256) {
        int r  = idx / HALO;
        int c  = idx - r * HALO;
        int hh = refl(h0 - 2 + r, HHN);
        int ww = refl(w0 - 2 + c, WWN);
        size_t gi = cbase + (size_t)hh * WWN + ww;
        ks[r * HSTR + c] = g_k[gi];
        vs[r * HSTR + c] = g_v[gi];
    }
    __syncthreads();

    const int h    = h0 + ty;
    const int wsub = tx * 4;                  // halo column base for this thread
    const size_t pix = (size_t)h * WWN + (w0 + wsub);

    const float4 q4 = *reinterpret_cast<const float4*>(&g_q[cbase + pix]);
    const float L2E = 1.44269504088896341f;
    float ql2[4] = { q4.x * L2E, q4.y * L2E, q4.z * L2E, q4.w * L2E };

    float num[4] = {0.f, 0.f, 0.f, 0.f};
    float den[4] = {0.f, 0.f, 0.f, 0.f};

    #pragma unroll
    for (int r = 0; r < 5; r++) {
        const float4* kp = reinterpret_cast<const float4*>(&ks[(ty + r) * HSTR + wsub]);
        const float4* vp = reinterpret_cast<const float4*>(&vs[(ty + r) * HSTR + wsub]);
        float4 k0 = kp[0], k1 = kp[1];
        float4 v0 = vp[0], v1 = vp[1];
        float kk[8] = { k0.x, k0.y, k0.z, k0.w, k1.x, k1.y, k1.z, k1.w };
        float vv[8] = { v0.x, v0.y, v0.z, v0.w, v1.x, v1.y, v1.z, v1.w };
        #pragma unroll
        for (int o = 0; o < 4; o++) {
            #pragma unroll
            for (int c = 0; c < 5; c++) {
                float e = ex2(ql2[o] * kk[o + c]);
                den[o] += e;
                num[o] = fmaf(e, vv[o + c], num[o]);
            }
        }
    }

    float4 r4 = make_float4(__fdividef(num[0], den[0]),
                            __fdividef(num[1], den[1]),
                            __fdividef(num[2], den[2]),
                            __fdividef(num[3], den[3]));
    *reinterpret_cast<float4*>(&out[cbase + pix]) = r4;
}

// -----------------------------------------------------------------------------
// Launch: 4-chunk two-stream pipeline. qkv is fma-bound, attn is MUFU-bound —
// complementary pipes, both ~78% issue-limited alone, so overlapping chunks
// fills each other's stall slots. Dependency is channel-local: attn chunk c
// (channels 64c..64c+63) needs only qkv chunk c (bg = 2c, 2c+1).
// Fork/join via events is graph-capturable. Streams/events are created in a
// static initializer (host-side, before the harness memory checkpoint); no
// device allocation happens inside kernel_launch.
// -----------------------------------------------------------------------------
#define NCHUNK 4

static cudaStream_t g_side;
static cudaEvent_t  g_evq[NCHUNK];
static cudaEvent_t  g_evdone;
static const bool g_stream_init = []() {
    cudaStreamCreateWithFlags(&g_side, cudaStreamNonBlocking);
    for (int i = 0; i < NCHUNK; i++)
        cudaEventCreateWithFlags(&g_evq[i], cudaEventDisableTiming);
    cudaEventCreateWithFlags(&g_evdone, cudaEventDisableTiming);
    return true;
}();

extern "C" void kernel_launch(void* const* d_in, const int* in_sizes, int n_in,
                              void* d_out, int out_size)
{
    const float* x  = (const float*)d_in[0];
    const float* wq = (const float*)d_in[1];
    const float* wk = (const float*)d_in[2];
    const float* wv = (const float*)d_in[3];
    float* out = (float*)d_out;
    (void)g_stream_init;

    for (int c = 0; c < NCHUNK; c++) {
        qkv_kernel<<<dim3(HHN, (BB * GG) / NCHUNK), 256>>>(x, wq, wk, wv,
                                                           c * (BB * GG) / NCHUNK);
        cudaEventRecord(g_evq[c], 0);
        cudaStreamWaitEvent(g_side, g_evq[c], 0);
        attn_kernel<<<dim3(WWN / 32, HHN / 32, (BB * CTOT) / NCHUNK),
                      256, 0, g_side>>>(out, c * (BB * CTOT) / NCHUNK);
    }
    cudaEventRecord(g_evdone, g_side);
    cudaStreamWaitEvent(0, g_evdone, 0);
}

// round 12
// speedup vs baseline: 1.2597x; 1.2597x over previous
#include <cuda_runtime.h>

// Problem constants (fixed shapes from reference):
//   x : (2, 128, 96, 96) f32, w{q,k,v} : (4, 32, 32) f32
//   K = 5 window, reflect pad 2, G = 4 groups of 32 channels.
#define BB   2
#define GG   4
#define CIN  32
#define CON  32
#define HHN  96
#define WWN  96
#define HWSZ (HHN * WWN)
#define CTOT 128

// Scratch for the three 1x1-conv outputs (q, k, v), each (B, 128, 96, 96).
__device__ __align__(256) float g_q[BB * CTOT * HWSZ];
__device__ __align__(256) float g_k[BB * CTOT * HWSZ];
__device__ __align__(256) float g_v[BB * CTOT * HWSZ];

// -----------------------------------------------------------------------------
// Kernel A: grouped 1x1 convs (q, k, v) fused — one CTA per (b, g, h) row.
// Measured-best variant (restored exactly). Ledger: f32x2 mainloop, smem-
// bounce epilogue, small-tile/high-occupancy, and chunked launches ALL
// regressed this kernel. Do not touch.
// -----------------------------------------------------------------------------
__global__ __launch_bounds__(256, 2) void qkv_kernel(
    const float* __restrict__ x,
    const float* __restrict__ wq,
    const float* __restrict__ wk,
    const float* __restrict__ wv)
{
    __shared__ float xs[CIN * WWN];            // 12 KB
    __shared__ float wqs[CON * 33];            // padded stride 33
    __shared__ float wks[CON * 33];
    __shared__ float wvs[CON * 33];

    const int h   = blockIdx.x;
    const int bg  = blockIdx.y;                // b*G + g
    const int g   = bg & (GG - 1);
    const int tid = threadIdx.x;

    // Stage x row: x[bg*32 + i][h][w]
    const float* xbase = x + (size_t)bg * CIN * HWSZ + (size_t)h * WWN;
    #pragma unroll
    for (int idx = tid; idx < CIN * (WWN / 4); idx += 256) {
        int i  = idx / (WWN / 4);
        int w4 = idx - i * (WWN / 4);
        reinterpret_cast<float4*>(xs)[i * (WWN / 4) + w4] =
            reinterpret_cast<const float4*>(xbase + (size_t)i * HWSZ)[w4];
    }
    // Stage weights of this group
    const float* wqg = wq + (size_t)g * CON * CIN;
    const float* wkg = wk + (size_t)g * CON * CIN;
    const float* wvg = wv + (size_t)g * CON * CIN;
    #pragma unroll
    for (int idx = tid; idx < CON * CIN; idx += 256) {
        int o = idx >> 5;
        int i = idx & 31;
        wqs[o * 33 + i] = wqg[idx];
        wks[o * 33 + i] = wkg[idx];
        wvs[o * 33 + i] = wvg[idx];
    }
    __syncthreads();

    const int o    = tid >> 3;            // 0..31 output channel
    const int wseg = (tid & 7) * 12;      // 12 consecutive w positions

    float aq[12], ak[12], av[12];
    #pragma unroll
    for (int u = 0; u < 12; u++) { aq[u] = 0.f; ak[u] = 0.f; av[u] = 0.f; }

    #pragma unroll 8
    for (int i = 0; i < CIN; i++) {
        const float wqv = wqs[o * 33 + i];
        const float wkv = wks[o * 33 + i];
        const float wvv = wvs[o * 33 + i];
        const float4* xv = reinterpret_cast<const float4*>(&xs[i * WWN + wseg]);
        float4 x0 = xv[0], x1 = xv[1], x2 = xv[2];
        float xr[12] = { x0.x, x0.y, x0.z, x0.w,
                         x1.x, x1.y, x1.z, x1.w,
                         x2.x, x2.y, x2.z, x2.w };
        #pragma unroll
        for (int u = 0; u < 12; u++) {
            aq[u] = fmaf(xr[u], wqv, aq[u]);
            ak[u] = fmaf(xr[u], wkv, ak[u]);
            av[u] = fmaf(xr[u], wvv, av[u]);
        }
    }

    const size_t obase = (size_t)(bg * CON + o) * HWSZ + (size_t)h * WWN + wseg;
    float4* qo = reinterpret_cast<float4*>(&g_q[obase]);
    float4* ko = reinterpret_cast<float4*>(&g_k[obase]);
    float4* vo = reinterpret_cast<float4*>(&g_v[obase]);
    #pragma unroll
    for (int u = 0; u < 3; u++) {
        qo[u] = make_float4(aq[4*u], aq[4*u+1], aq[4*u+2], aq[4*u+3]);
        ko[u] = make_float4(ak[4*u], ak[4*u+1], ak[4*u+2], ak[4*u+3]);
        vo[u] = make_float4(av[4*u], av[4*u+1], av[4*u+2], av[4*u+3]);
    }
}

// -----------------------------------------------------------------------------
// Kernel B: per-channel 5x5 windowed softmax with reflect indexing.
// Proven shape (R10): 256 threads, 4 outputs/thread, LDS.128 halo stride 44.
// NEW: hybrid exp — 6 of the 25 window terms per output (row r=0 and
// (r=2,c=2); compile-time choice after unrolling) are computed with a
// pure-FMA exp2 polynomial instead of MUFU ex2. MUFU was the binding pipe
// (rt_SMSP=8, floor 13.8us) while fma sat at 30%; offloading ~24% of exps
// lowers the MUFU floor to ~10.5us at modest issue cost.
// Poly: magic-number round-to-int, degree-4 Taylor of 2^f on [-0.5,0.5]
// (rel err ~4e-5; |t| <= ~15 is far inside the magic-trick domain).
// -----------------------------------------------------------------------------
__device__ __forceinline__ int refl(int i, int n) {
    return i < 0 ? -i : (i >= n ? 2 * n - 2 - i : i);
}

__device__ __forceinline__ float ex2(float x) {
    float y;
    asm("ex2.approx.ftz.f32 %0, %1;" : "=f"(y) : "f"(x));
    return y;
}

__device__ __forceinline__ float exp2_poly(float t) {
    const float MAGIC = 12582912.0f;           // 1.5 * 2^23
    float tr = t + MAGIC;                      // low bits now hold round(t)
    float f  = t - (tr - MAGIC);               // f in [-0.5, 0.5]
    int   sb = (__float_as_int(tr) + (127 - 0x4B400000)) << 23;  // 2^n bits
    float p  = fmaf(f, 0.00961812911f, 0.05550410866f);
    p = fmaf(f, p, 0.24022650696f);
    p = fmaf(f, p, 0.69314718056f);
    p = fmaf(f, p, 1.0f);
    return p * __int_as_float(sb);
}

#define HALO 36
#define HSTR 44

__global__ __launch_bounds__(256) void attn_kernel(float* __restrict__ out)
{
    __shared__ __align__(16) float ks[HALO * HSTR];   // 6.3 KB
    __shared__ __align__(16) float vs[HALO * HSTR];

    const int ch  = blockIdx.z;               // 0..255 = b*128 + channel
    const int h0  = blockIdx.y * 32;
    const int w0  = blockIdx.x * 32;
    const int tid = threadIdx.x;
    const int tx  = tid & 7;                  // 8 threads across w (4 outputs each)
    const int ty  = tid >> 3;                 // 32 rows

    const size_t cbase = (size_t)ch * HWSZ;

    // Stage k/v halos (36x36 window, reflect at global borders).
    #pragma unroll
    for (int idx = tid; idx < HALO * HALO; idx += 256) {
        int r  = idx / HALO;
        int c  = idx - r * HALO;
        int hh = refl(h0 - 2 + r, HHN);
        int ww = refl(w0 - 2 + c, WWN);
        size_t gi = cbase + (size_t)hh * WWN + ww;
        ks[r * HSTR + c] = g_k[gi];
        vs[r * HSTR + c] = g_v[gi];
    }
    __syncthreads();

    const int h    = h0 + ty;
    const int wsub = tx * 4;                  // halo column base for this thread
    const size_t pix = (size_t)h * WWN + (w0 + wsub);

    const float4 q4 = *reinterpret_cast<const float4*>(&g_q[cbase + pix]);
    const float L2E = 1.44269504088896341f;
    float ql2[4] = { q4.x * L2E, q4.y * L2E, q4.z * L2E, q4.w * L2E };

    float num[4] = {0.f, 0.f, 0.f, 0.f};
    float den[4] = {0.f, 0.f, 0.f, 0.f};

    #pragma unroll
    for (int r = 0; r < 5; r++) {
        const float4* kp = reinterpret_cast<const float4*>(&ks[(ty + r) * HSTR + wsub]);
        const float4* vp = reinterpret_cast<const float4*>(&vs[(ty + r) * HSTR + wsub]);
        float4 k0 = kp[0], k1 = kp[1];
        float4 v0 = vp[0], v1 = vp[1];
        float kk[8] = { k0.x, k0.y, k0.z, k0.w, k1.x, k1.y, k1.z, k1.w };
        float vv[8] = { v0.x, v0.y, v0.z, v0.w, v1.x, v1.y, v1.z, v1.w };
        #pragma unroll
        for (int o = 0; o < 4; o++) {
            #pragma unroll
            for (int c = 0; c < 5; c++) {
                float t = ql2[o] * kk[o + c];
                // Static pipe split: 6/25 terms on the fma pipe, rest on MUFU.
                float e = (r == 0 || (r == 2 && c == 2)) ? exp2_poly(t) : ex2(t);
                den[o] += e;
                num[o] = fmaf(e, vv[o + c], num[o]);
            }
        }
    }

    float4 r4 = make_float4(__fdividef(num[0], den[0]),
                            __fdividef(num[1], den[1]),
                            __fdividef(num[2], den[2]),
                            __fdividef(num[3], den[3]));
    *reinterpret_cast<float4*>(&out[cbase + pix]) = r4;
}

// -----------------------------------------------------------------------------
// Launch: two kernels, single stream (R10 proven; chunked two-stream pipeline
// measured 49.7us — chunk occupancy/tail losses exceed any overlap gain).
// Inputs (metadata order): x, wq, wk, wv — all float32. Output float32.
// -----------------------------------------------------------------------------
extern "C" void kernel_launch(void* const* d_in, const int* in_sizes, int n_in,
                              void* d_out, int out_size)
{
    const float* x  = (const float*)d_in[0];
    const float* wq = (const float*)d_in[1];
    const float* wk = (const float*)d_in[2];
    const float* wv = (const float*)d_in[3];
    float* out = (float*)d_out;

    qkv_kernel<<<dim3(HHN, BB * GG), 256>>>(x, wq, wk, wv);
    attn_kernel<<<dim3(WWN / 32, HHN / 32, BB * CTOT), dim3(256)>>>(out);
}

// round 13
// speedup vs baseline: 1.3209x; 1.0485x over previous
#include <cuda_runtime.h>

// Problem constants (fixed shapes from reference):
//   x : (2, 128, 96, 96) f32, w{q,k,v} : (4, 32, 32) f32
//   K = 5 window, reflect pad 2, G = 4 groups of 32 channels.
#define BB   2
#define GG   4
#define CIN  32
#define CON  32
#define HHN  96
#define WWN  96
#define HWSZ (HHN * WWN)
#define CTOT 128

// Scratch for the three 1x1-conv outputs (q, k, v), each (B, 128, 96, 96).
__device__ __align__(256) float g_q[BB * CTOT * HWSZ];
__device__ __align__(256) float g_k[BB * CTOT * HWSZ];
__device__ __align__(256) float g_v[BB * CTOT * HWSZ];

// -----------------------------------------------------------------------------
// Kernel A: grouped 1x1 convs (q, k, v) fused — one CTA per (b, g, h) row.
// VERBATIM restore of the configuration that measured 16.3us (R4 bench of the
// R3-proposal kernel): scalar FFMA mainloop, scalar x staging, and PLAIN
// __launch_bounds__(256) — the (256,2) occupancy clause measurably regressed
// this kernel to 19.4us and was carried forward by a ledger mislabel.
// Full ledger of regressions: (256,2) clause, f32x2 mainloop, smem-bounce
// epilogue, small-tile/high-occupancy, chunked launches. Do not touch.
// -----------------------------------------------------------------------------
__global__ __launch_bounds__(256) void qkv_kernel(
    const float* __restrict__ x,
    const float* __restrict__ wq,
    const float* __restrict__ wk,
    const float* __restrict__ wv)
{
    __shared__ float xs[CIN * WWN];            // 12 KB
    __shared__ float wqs[CON * 33];            // padded stride 33
    __shared__ float wks[CON * 33];
    __shared__ float wvs[CON * 33];

    const int h   = blockIdx.x;
    const int bg  = blockIdx.y;                // b*G + g
    const int g   = bg & (GG - 1);
    const int tid = threadIdx.x;

    // Stage x row: x[bg*32 + i][h][w]
    const float* xbase = x + (size_t)bg * CIN * HWSZ + (size_t)h * WWN;
    #pragma unroll
    for (int idx = tid; idx < CIN * WWN; idx += 256) {
        int i = idx / WWN;
        int w = idx - i * WWN;
        xs[idx] = xbase[(size_t)i * HWSZ + w];
    }
    // Stage weights of this group
    const float* wqg = wq + (size_t)g * CON * CIN;
    const float* wkg = wk + (size_t)g * CON * CIN;
    const float* wvg = wv + (size_t)g * CON * CIN;
    #pragma unroll
    for (int idx = tid; idx < CON * CIN; idx += 256) {
        int o = idx >> 5;
        int i = idx & 31;
        wqs[o * 33 + i] = wqg[idx];
        wks[o * 33 + i] = wkg[idx];
        wvs[o * 33 + i] = wvg[idx];
    }
    __syncthreads();

    const int o    = tid >> 3;            // 0..31 output channel
    const int wseg = (tid & 7) * 12;      // 12 consecutive w positions

    float aq[12], ak[12], av[12];
    #pragma unroll
    for (int u = 0; u < 12; u++) { aq[u] = 0.f; ak[u] = 0.f; av[u] = 0.f; }

    #pragma unroll 8
    for (int i = 0; i < CIN; i++) {
        const float wqv = wqs[o * 33 + i];
        const float wkv = wks[o * 33 + i];
        const float wvv = wvs[o * 33 + i];
        const float4* xv = reinterpret_cast<const float4*>(&xs[i * WWN + wseg]);
        float4 x0 = xv[0], x1 = xv[1], x2 = xv[2];
        float xr[12] = { x0.x, x0.y, x0.z, x0.w,
                         x1.x, x1.y, x1.z, x1.w,
                         x2.x, x2.y, x2.z, x2.w };
        #pragma unroll
        for (int u = 0; u < 12; u++) {
            aq[u] = fmaf(xr[u], wqv, aq[u]);
            ak[u] = fmaf(xr[u], wkv, ak[u]);
            av[u] = fmaf(xr[u], wvv, av[u]);
        }
    }

    const size_t obase = (size_t)(bg * CON + o) * HWSZ + (size_t)h * WWN + wseg;
    float4* qo = reinterpret_cast<float4*>(&g_q[obase]);
    float4* ko = reinterpret_cast<float4*>(&g_k[obase]);
    float4* vo = reinterpret_cast<float4*>(&g_v[obase]);
    #pragma unroll
    for (int u = 0; u < 3; u++) {
        qo[u] = make_float4(aq[4*u], aq[4*u+1], aq[4*u+2], aq[4*u+3]);
        ko[u] = make_float4(ak[4*u], ak[4*u+1], ak[4*u+2], ak[4*u+3]);
        vo[u] = make_float4(av[4*u], av[4*u+1], av[4*u+2], av[4*u+3]);
    }
}

// -----------------------------------------------------------------------------
// Kernel B: per-channel 5x5 windowed softmax with reflect indexing.
// VERBATIM restore of the measured-best variant (R10, 16.8us): 256 threads
// (8 tx x 32 ty), 4 consecutive w outputs/thread, LDS.128 halo stride 44,
// pure-MUFU single-pass softmax (log2e folded into q).
// Ledger of regressions: 128-thread/8-output tiles (21.0us), hybrid poly-exp
// pipe split (19.9us — reg pressure killed occupancy), chunked launches.
// -----------------------------------------------------------------------------
__device__ __forceinline__ int refl(int i, int n) {
    return i < 0 ? -i : (i >= n ? 2 * n - 2 - i : i);
}

__device__ __forceinline__ float ex2(float x) {
    float y;
    asm("ex2.approx.ftz.f32 %0, %1;" : "=f"(y) : "f"(x));
    return y;
}

#define HALO 36
#define HSTR 44

__global__ __launch_bounds__(256) void attn_kernel(float* __restrict__ out)
{
    __shared__ __align__(16) float ks[HALO * HSTR];   // 6.3 KB
    __shared__ __align__(16) float vs[HALO * HSTR];

    const int ch  = blockIdx.z;               // 0..255 = b*128 + channel
    const int h0  = blockIdx.y * 32;
    const int w0  = blockIdx.x * 32;
    const int tid = threadIdx.x;
    const int tx  = tid & 7;                  // 8 threads across w (4 outputs each)
    const int ty  = tid >> 3;                 // 32 rows

    const size_t cbase = (size_t)ch * HWSZ;

    // Stage k/v halos (36x36 window, reflect at global borders).
    #pragma unroll
    for (int idx = tid; idx < HALO * HALO; idx += 256) {
        int r  = idx / HALO;
        int c  = idx - r * HALO;
        int hh = refl(h0 - 2 + r, HHN);
        int ww = refl(w0 - 2 + c, WWN);
        size_t gi = cbase + (size_t)hh * WWN + ww;
        ks[r * HSTR + c] = g_k[gi];
        vs[r * HSTR + c] = g_v[gi];
    }
    __syncthreads();

    const int h    = h0 + ty;
    const int wsub = tx * 4;                  // halo column base for this thread
    const size_t pix = (size_t)h * WWN + (w0 + wsub);

    const float4 q4 = *reinterpret_cast<const float4*>(&g_q[cbase + pix]);
    const float L2E = 1.44269504088896341f;
    float ql2[4] = { q4.x * L2E, q4.y * L2E, q4.z * L2E, q4.w * L2E };

    float num[4] = {0.f, 0.f, 0.f, 0.f};
    float den[4] = {0.f, 0.f, 0.f, 0.f};

    #pragma unroll
    for (int r = 0; r < 5; r++) {
        const float4* kp = reinterpret_cast<const float4*>(&ks[(ty + r) * HSTR + wsub]);
        const float4* vp = reinterpret_cast<const float4*>(&vs[(ty + r) * HSTR + wsub]);
        float4 k0 = kp[0], k1 = kp[1];
        float4 v0 = vp[0], v1 = vp[1];
        float kk[8] = { k0.x, k0.y, k0.z, k0.w, k1.x, k1.y, k1.z, k1.w };
        float vv[8] = { v0.x, v0.y, v0.z, v0.w, v1.x, v1.y, v1.z, v1.w };
        #pragma unroll
        for (int o = 0; o < 4; o++) {
            #pragma unroll
            for (int c = 0; c < 5; c++) {
                float e = ex2(ql2[o] * kk[o + c]);
                den[o] += e;
                num[o] = fmaf(e, vv[o + c], num[o]);
            }
        }
    }

    float4 r4 = make_float4(__fdividef(num[0], den[0]),
                            __fdividef(num[1], den[1]),
                            __fdividef(num[2], den[2]),
                            __fdividef(num[3], den[3]));
    *reinterpret_cast<float4*>(&out[cbase + pix]) = r4;
}

// -----------------------------------------------------------------------------
// Launch: two kernels, single stream (chunked two-stream pipeline measured
// 49.7us — chunk occupancy/tail losses exceed any overlap gain).
// Inputs (metadata order): x, wq, wk, wv — all float32. Output float32.
// -----------------------------------------------------------------------------
extern "C" void kernel_launch(void* const* d_in, const int* in_sizes, int n_in,
                              void* d_out, int out_size)
{
    const float* x  = (const float*)d_in[0];
    const float* wq = (const float*)d_in[1];
    const float* wk = (const float*)d_in[2];
    const float* wv = (const float*)d_in[3];
    float* out = (float*)d_out;

    qkv_kernel<<<dim3(HHN, BB * GG), 256>>>(x, wq, wk, wv);
    attn_kernel<<<dim3(WWN / 32, HHN / 32, BB * CTOT), dim3(256)>>>(out);
}

// round 14
// speedup vs baseline: 1.4058x; 1.0643x over previous
#include <cuda_runtime.h>

// Problem constants (fixed shapes from reference):
//   x : (2, 128, 96, 96) f32, w{q,k,v} : (4, 32, 32) f32
//   K = 5 window, reflect pad 2, G = 4 groups of 32 channels.
#define BB   2
#define GG   4
#define CIN  32
#define CON  32
#define HHN  96
#define WWN  96
#define HWSZ (HHN * WWN)
#define CTOT 128

// Scratch for the three 1x1-conv outputs (q, k, v), each (B, 128, 96, 96).
__device__ __align__(256) float g_q[BB * CTOT * HWSZ];
__device__ __align__(256) float g_k[BB * CTOT * HWSZ];
__device__ __align__(256) float g_v[BB * CTOT * HWSZ];

// -----------------------------------------------------------------------------
// Kernel A: grouped 1x1 convs (q, k, v) fused — one CTA per (b, g, h) row.
// Base = R10 config (best measured qkv, 18.1us): scalar FFMA, float4 x
// staging, direct stores. Two surgical changes this round:
//   (1) weights staged as one padded float4 triple (wq,wk,wv,0) -> mainloop
//       issues drop 42 -> 40 per i-step (1 LDS.128 replaces 3 scalar LDS);
//   (2) __launch_bounds__(256,3): 3 resident CTAs cut the 768-CTA grid from
//       2.59 to 1.73 waves and cover the staging prologue latency.
// Ledger of regressions: plain bounds (20.0us), f32x2 mainloop, smem-bounce
// epilogue, small-tile split, chunked launches.
// -----------------------------------------------------------------------------
__global__ __launch_bounds__(256, 3) void qkv_kernel(
    const float* __restrict__ x,
    const float* __restrict__ wq,
    const float* __restrict__ wk,
    const float* __restrict__ wv)
{
    __shared__ float xs[CIN * WWN];                    // 12 KB
    __shared__ __align__(16) float4 wall[CON * 33];    // packed (wq,wk,wv,0), 16.9 KB total smem

    const int h   = blockIdx.x;
    const int bg  = blockIdx.y;                // b*G + g
    const int g   = bg & (GG - 1);
    const int tid = threadIdx.x;

    // Stage x row with float4 loads: x[bg*32 + i][h][w]
    const float* xbase = x + (size_t)bg * CIN * HWSZ + (size_t)h * WWN;
    #pragma unroll
    for (int idx = tid; idx < CIN * (WWN / 4); idx += 256) {
        int i  = idx / (WWN / 4);
        int w4 = idx - i * (WWN / 4);
        reinterpret_cast<float4*>(xs)[i * (WWN / 4) + w4] =
            reinterpret_cast<const float4*>(xbase + (size_t)i * HWSZ)[w4];
    }
    // Stage weights of this group as packed triples
    const float* wqg = wq + (size_t)g * CON * CIN;
    const float* wkg = wk + (size_t)g * CON * CIN;
    const float* wvg = wv + (size_t)g * CON * CIN;
    #pragma unroll
    for (int idx = tid; idx < CON * CIN; idx += 256) {
        int o = idx >> 5;
        int i = idx & 31;
        wall[o * 33 + i] = make_float4(wqg[idx], wkg[idx], wvg[idx], 0.f);
    }
    __syncthreads();

    const int o    = tid >> 3;            // 0..31 output channel
    const int wseg = (tid & 7) * 12;      // 12 consecutive w positions

    float aq[12], ak[12], av[12];
    #pragma unroll
    for (int u = 0; u < 12; u++) { aq[u] = 0.f; ak[u] = 0.f; av[u] = 0.f; }

    #pragma unroll 8
    for (int i = 0; i < CIN; i++) {
        const float4 w3 = wall[o * 33 + i];
        const float4* xv = reinterpret_cast<const float4*>(&xs[i * WWN + wseg]);
        float4 x0 = xv[0], x1 = xv[1], x2 = xv[2];
        float xr[12] = { x0.x, x0.y, x0.z, x0.w,
                         x1.x, x1.y, x1.z, x1.w,
                         x2.x, x2.y, x2.z, x2.w };
        #pragma unroll
        for (int u = 0; u < 12; u++) {
            aq[u] = fmaf(xr[u], w3.x, aq[u]);
            ak[u] = fmaf(xr[u], w3.y, ak[u]);
            av[u] = fmaf(xr[u], w3.z, av[u]);
        }
    }

    const size_t obase = (size_t)(bg * CON + o) * HWSZ + (size_t)h * WWN + wseg;
    float4* qo = reinterpret_cast<float4*>(&g_q[obase]);
    float4* ko = reinterpret_cast<float4*>(&g_k[obase]);
    float4* vo = reinterpret_cast<float4*>(&g_v[obase]);
    #pragma unroll
    for (int u = 0; u < 3; u++) {
        qo[u] = make_float4(aq[4*u], aq[4*u+1], aq[4*u+2], aq[4*u+3]);
        ko[u] = make_float4(ak[4*u], ak[4*u+1], ak[4*u+2], ak[4*u+3]);
        vo[u] = make_float4(av[4*u], av[4*u+1], av[4*u+2], av[4*u+3]);
    }
}

// -----------------------------------------------------------------------------
// Kernel B: per-channel 5x5 windowed softmax with reflect indexing.
// VERBATIM restore of the measured-best variant (R10, 16.8us): 256 threads
// (8 tx x 32 ty), 4 consecutive w outputs/thread, LDS.128 halo stride 44,
// pure-MUFU single-pass softmax (log2e folded into q).
// Ledger of regressions: 128-thread/8-output tiles (21.0us), hybrid poly-exp
// pipe split (19.9us — reg pressure killed occupancy), chunked launches.
// -----------------------------------------------------------------------------
__device__ __forceinline__ int refl(int i, int n) {
    return i < 0 ? -i : (i >= n ? 2 * n - 2 - i : i);
}

__device__ __forceinline__ float ex2(float x) {
    float y;
    asm("ex2.approx.ftz.f32 %0, %1;" : "=f"(y) : "f"(x));
    return y;
}

#define HALO 36
#define HSTR 44

__global__ __launch_bounds__(256) void attn_kernel(float* __restrict__ out)
{
    __shared__ __align__(16) float ks[HALO * HSTR];   // 6.3 KB
    __shared__ __align__(16) float vs[HALO * HSTR];

    const int ch  = blockIdx.z;               // 0..255 = b*128 + channel
    const int h0  = blockIdx.y * 32;
    const int w0  = blockIdx.x * 32;
    const int tid = threadIdx.x;
    const int tx  = tid & 7;                  // 8 threads across w (4 outputs each)
    const int ty  = tid >> 3;                 // 32 rows

    const size_t cbase = (size_t)ch * HWSZ;

    // Stage k/v halos (36x36 window, reflect at global borders).
    #pragma unroll
    for (int idx = tid; idx < HALO * HALO; idx += 256) {
        int r  = idx / HALO;
        int c  = idx - r * HALO;
        int hh = refl(h0 - 2 + r, HHN);
        int ww = refl(w0 - 2 + c, WWN);
        size_t gi = cbase + (size_t)hh * WWN + ww;
        ks[r * HSTR + c] = g_k[gi];
        vs[r * HSTR + c] = g_v[gi];
    }
    __syncthreads();

    const int h    = h0 + ty;
    const int wsub = tx * 4;                  // halo column base for this thread
    const size_t pix = (size_t)h * WWN + (w0 + wsub);

    const float4 q4 = *reinterpret_cast<const float4*>(&g_q[cbase + pix]);
    const float L2E = 1.44269504088896341f;
    float ql2[4] = { q4.x * L2E, q4.y * L2E, q4.z * L2E, q4.w * L2E };

    float num[4] = {0.f, 0.f, 0.f, 0.f};
    float den[4] = {0.f, 0.f, 0.f, 0.f};

    #pragma unroll
    for (int r = 0; r < 5; r++) {
        const float4* kp = reinterpret_cast<const float4*>(&ks[(ty + r) * HSTR + wsub]);
        const float4* vp = reinterpret_cast<const float4*>(&vs[(ty + r) * HSTR + wsub]);
        float4 k0 = kp[0], k1 = kp[1];
        float4 v0 = vp[0], v1 = vp[1];
        float kk[8] = { k0.x, k0.y, k0.z, k0.w, k1.x, k1.y, k1.z, k1.w };
        float vv[8] = { v0.x, v0.y, v0.z, v0.w, v1.x, v1.y, v1.z, v1.w };
        #pragma unroll
        for (int o = 0; o < 4; o++) {
            #pragma unroll
            for (int c = 0; c < 5; c++) {
                float e = ex2(ql2[o] * kk[o + c]);
                den[o] += e;
                num[o] = fmaf(e, vv[o + c], num[o]);
            }
        }
    }

    float4 r4 = make_float4(__fdividef(num[0], den[0]),
                            __fdividef(num[1], den[1]),
                            __fdividef(num[2], den[2]),
                            __fdividef(num[3], den[3]));
    *reinterpret_cast<float4*>(&out[cbase + pix]) = r4;
}

// -----------------------------------------------------------------------------
// Launch: two kernels, single stream (chunked two-stream pipeline measured
// 49.7us — chunk occupancy/tail losses exceed any overlap gain).
// Inputs (metadata order): x, wq, wk, wv — all float32. Output float32.
// -----------------------------------------------------------------------------
extern "C" void kernel_launch(void* const* d_in, const int* in_sizes, int n_in,
                              void* d_out, int out_size)
{
    const float* x  = (const float*)d_in[0];
    const float* wq = (const float*)d_in[1];
    const float* wk = (const float*)d_in[2];
    const float* wv = (const float*)d_in[3];
    float* out = (float*)d_out;

    qkv_kernel<<<dim3(HHN, BB * GG), 256>>>(x, wq, wk, wv);
    attn_kernel<<<dim3(WWN / 32, HHN / 32, BB * CTOT), dim3(256)>>>(out);
}